// round 8
// baseline (speedup 1.0000x reference)
#include <cuda_runtime.h>
#include <cuda_bf16.h>

// Problem constants (reference: N=100000, E=1000000, D=64)
#define MAXN 100000
#define MAXE 1000000
#define DIMF 64

typedef unsigned long long ull;

// Scratch (device globals; no allocation allowed)
__device__ float g_agg[MAXN * DIMF];
__device__ float g_h1[MAXN * DIMF];
__device__ float g_h2[MAXN * DIMF];
__device__ int   g_cnt[MAXN];
__device__ int   g_rowptr[MAXN + 1];
__device__ int   g_cursor[MAXN];
__device__ int2  g_edata[MAXE];          // {src, float_bits(w)} grouped by dst
__device__ int   g_bsum[512];

// ---------------------------------------------------------------------------
// f32x2 helpers (two IEEE fp32 ops per issue; bit-exact vs scalar FFMA)
// ---------------------------------------------------------------------------
__device__ __forceinline__ void fma2(ull& acc, ull a, ull b) {
    asm("fma.rn.f32x2 %0, %1, %2, %0;" : "+l"(acc) : "l"(a), "l"(b));
}
__device__ __forceinline__ ull pack2(float lo, float hi) {
    ull r; asm("mov.b64 %0, {%1, %2};" : "=l"(r) : "f"(lo), "f"(hi)); return r;
}
__device__ __forceinline__ float2 unpack2(ull v) {
    float2 r; asm("mov.b64 {%0, %1}, %2;" : "=f"(r.x), "=f"(r.y) : "l"(v)); return r;
}
__device__ __forceinline__ void lds_v2u64(ull& a, ull& b, unsigned addr) {
    asm("ld.shared.v2.u64 {%0, %1}, [%2];" : "=l"(a), "=l"(b) : "r"(addr));
}

// ---------------------------------------------------------------------------
// CSR build: histogram -> exclusive scan -> fill   (unchanged R7)
// ---------------------------------------------------------------------------
__global__ void zero_cnt_kernel(int* __restrict__ cnt, int N) {
    int i = blockIdx.x * blockDim.x + threadIdx.x;
    if (i < N) cnt[i] = 0;
}

__global__ void hist_kernel(const int* __restrict__ dst, int* __restrict__ cnt, int E) {
    int e = blockIdx.x * blockDim.x + threadIdx.x;
    if (e < E) atomicAdd(&cnt[dst[e]], 1);
}

__global__ void scan_partial_kernel(const int* __restrict__ cnt, int* __restrict__ bsum, int N) {
    __shared__ int sm[256];
    int i = blockIdx.x * 256 + threadIdx.x;
    sm[threadIdx.x] = (i < N) ? cnt[i] : 0;
    __syncthreads();
    for (int s = 128; s > 0; s >>= 1) {
        if (threadIdx.x < s) sm[threadIdx.x] += sm[threadIdx.x + s];
        __syncthreads();
    }
    if (threadIdx.x == 0) bsum[blockIdx.x] = sm[0];
}

__global__ void scan_top_kernel(int* __restrict__ bsum, int NB) {
    __shared__ int sm[512];
    int t = threadIdx.x;
    int v = (t < NB) ? bsum[t] : 0;
    sm[t] = v;
    __syncthreads();
    for (int s = 1; s < 512; s <<= 1) {
        int add = (t >= s) ? sm[t - s] : 0;
        __syncthreads();
        sm[t] += add;
        __syncthreads();
    }
    if (t < NB) bsum[t] = sm[t] - v;   // exclusive
}

__global__ void scan_final_kernel(const int* __restrict__ cnt,
                                  const int* __restrict__ bsum,
                                  int* __restrict__ rowptr,
                                  int* __restrict__ cursor, int N) {
    __shared__ int sm[256];
    int t = threadIdx.x;
    int i = blockIdx.x * 256 + t;
    int v = (i < N) ? cnt[i] : 0;
    sm[t] = v;
    __syncthreads();
    for (int s = 1; s < 256; s <<= 1) {
        int add = (t >= s) ? sm[t - s] : 0;
        __syncthreads();
        sm[t] += add;
        __syncthreads();
    }
    int val = bsum[blockIdx.x] + sm[t] - v;   // exclusive prefix
    if (i < N) {
        rowptr[i] = val;
        cursor[i] = val;
    } else if (i == N) {
        rowptr[N] = val;                      // == E
    }
}

__global__ void fill_kernel(const int* __restrict__ src, const int* __restrict__ dst,
                            const float* __restrict__ ew,
                            int* __restrict__ cursor, int2* __restrict__ edata, int E) {
    int e = blockIdx.x * blockDim.x + threadIdx.x;
    if (e >= E) return;
    int d = dst[e];
    int p = atomicAdd(&cursor[d], 1);
    edata[p] = make_int2(src[e], __float_as_int(ew[e]));
}

// ---------------------------------------------------------------------------
// Gather-aggregate: agg[n] = x[n] + sum_{e in csr(n)} x[src_e] * w_e
// (unchanged R6/R7 winner)
// ---------------------------------------------------------------------------
__global__ void gather_kernel(const float4* __restrict__ x4,
                              const int* __restrict__ rowptr,
                              const int2* __restrict__ edata,
                              float4* __restrict__ agg, int N) {
    int idx = blockIdx.x * blockDim.x + threadIdx.x;
    int n = idx >> 4;
    if (n >= N) return;
    int c = idx & 15;
    unsigned gmask = 0xFFFFu << (threadIdx.x & 16);   // this 16-lane group

    int beg = __ldg(rowptr + n);
    int end = __ldg(rowptr + n + 1);
    float4 acc = x4[(size_t)n * 16 + c];    // GIN identity term

    for (int base = beg; base < end; base += 16) {
        int e = base + c;
        int2 ed = (e < end) ? __ldg(edata + e) : make_int2(0, 0);
        #pragma unroll
        for (int i = 0; i < 16; i++) {
            int s   = __shfl_sync(gmask, ed.x, i, 16);
            float w = __int_as_float(__shfl_sync(gmask, ed.y, i, 16));
            float4 v = __ldg(&x4[(size_t)s * 16 + c]);
            acc.x += v.x * w; acc.y += v.y * w;
            acc.z += v.z * w; acc.w += v.w * w;
        }
    }
    agg[(size_t)n * 16 + c] = acc;
}

// ---------------------------------------------------------------------------
// Fused MLP, f32x2 edition: out = [relu]( relu(agg @ W1 + b1) @ W2 + b2 )
//
// Accumulators are column-pairs in 64-bit regs (fma.rn.f32x2 -> 2 fp32
// FMAs/issue, bit-exact). Weights kept natural row-major in smem; one
// ld.shared.v2.u64 of w[k][c0..c3] yields both packed weight pairs with no
// MOVs. Activations staged DUPLICATED ((v,v) float2), row-major with stride
// 66/130 float2 (132/260 words = 4 banks mod 32 -> optimal 2-phase LDS.128,
// conflict-free): one LDS.128 per (row, k-pair) gives two ready operands.
// hid (duplicated) exactly reuses the in+w1 region. Smem 65.5KB/97.8KB ->
// 3 / 2 blocks per SM.
// ---------------------------------------------------------------------------
template<int H, bool RELU_OUT>
__global__ void __launch_bounds__(256, 2) mlp_kernel(
        const float4* __restrict__ agg4,
        const float4* __restrict__ w1, const float* __restrict__ b1,
        const float4* __restrict__ w2, const float* __restrict__ b2,
        float4* __restrict__ out4, int N) {
    constexpr int TR   = 64;        // rows per block
    constexpr int INS2 = 66;        // in_dup row stride (float2)
    constexpr int HS2  = H + 2;     // hid_dup row stride (float2)
    constexpr int NP   = H / 64;    // col passes in GEMM1

    // byte offsets into dynamic smem
    constexpr unsigned IN_OFF  = 0;
    constexpr unsigned W1_OFF  = TR * INS2 * 8;              // 33792
    constexpr unsigned W2_OFF  = W1_OFF + 64 * H * 4;
    constexpr unsigned B1_OFF  = W2_OFF + H * 64 * 4;
    constexpr unsigned B2_OFF  = B1_OFF + H * 4;
    static_assert(TR * HS2 * 8 <= W2_OFF, "hid_dup must fit in in+w1 region");

    extern __shared__ float sm[];
    unsigned sbase = (unsigned)__cvta_generic_to_shared(sm);
    float* w1n = (float*)((char*)sm + W1_OFF);
    float* w2n = (float*)((char*)sm + W2_OFF);
    float* b1s = (float*)((char*)sm + B1_OFF);
    float* b2s = (float*)((char*)sm + B2_OFF);

    int tid  = threadIdx.x;
    int row0 = blockIdx.x * TR;
    int nrows = N - row0; if (nrows > TR) nrows = TR;

    // Weights: natural layout, straight coalesced conflict-free float4 copy
    for (int i = tid; i < 64 * H / 4; i += 256) ((float4*)w1n)[i] = w1[i];
    for (int i = tid; i < H * 64 / 4; i += 256) ((float4*)w2n)[i] = w2[i];
    if (tid < H)  b1s[tid] = b1[tid];
    if (tid < 64) b2s[tid] = b2[tid];

    // Stage input duplicated: in_dup[r][k] = (v, v)
    for (int i = tid; i < TR * 16; i += 256) {
        int r = i >> 4, k4 = i & 15;
        float4 v = make_float4(0.f, 0.f, 0.f, 0.f);
        if (r < nrows) v = agg4[(size_t)(row0 + r) * 16 + k4];
        float2* p = (float2*)((char*)sm + IN_OFF) + r * INS2 + k4 * 4;
        p[0] = make_float2(v.x, v.x); p[1] = make_float2(v.y, v.y);
        p[2] = make_float2(v.z, v.z); p[3] = make_float2(v.w, v.w);
    }
    __syncthreads();

    const int rg = tid & 15;   // rows rg + 16j
    const int cg = tid >> 4;   // col group (uniform per half-warp -> broadcast)

    // GEMM1: acc1 = in @ W1 + b1, column-pair packed
    ull acc1[NP][4][2];
    #pragma unroll
    for (int p = 0; p < NP; p++) {
        int c0 = (p * 16 + cg) * 4;
        ull i0 = pack2(b1s[c0], b1s[c0 + 1]);
        ull i1 = pack2(b1s[c0 + 2], b1s[c0 + 3]);
        #pragma unroll
        for (int j = 0; j < 4; j++) { acc1[p][j][0] = i0; acc1[p][j][1] = i1; }
    }
    #pragma unroll 4
    for (int k2 = 0; k2 < 32; ++k2) {     // k = 2k2, 2k2+1
        ull ivA[4], ivB[4];
        #pragma unroll
        for (int j = 0; j < 4; j++)
            lds_v2u64(ivA[j], ivB[j],
                      sbase + IN_OFF + (unsigned)(rg + 16 * j) * (INS2 * 8) + k2 * 16);
        #pragma unroll
        for (int p = 0; p < NP; p++) {
            int c0 = (p * 16 + cg) * 4;
            ull wA0, wA1, wB0, wB1;
            lds_v2u64(wA0, wA1, sbase + W1_OFF + (unsigned)(2 * k2)     * (H * 4) + c0 * 4);
            lds_v2u64(wB0, wB1, sbase + W1_OFF + (unsigned)(2 * k2 + 1) * (H * 4) + c0 * 4);
            #pragma unroll
            for (int j = 0; j < 4; j++) {
                fma2(acc1[p][j][0], ivA[j], wA0);
                fma2(acc1[p][j][1], ivA[j], wA1);
                fma2(acc1[p][j][0], ivB[j], wB0);
                fma2(acc1[p][j][1], ivB[j], wB1);
            }
        }
    }
    __syncthreads();   // all reads of in_dup / w1n complete

    // Store relu(hid) duplicated: hid_dup[r][h] = (v, v)  (reuses region)
    #pragma unroll
    for (int p = 0; p < NP; p++) {
        int c0 = (p * 16 + cg) * 4;
        #pragma unroll
        for (int j = 0; j < 4; j++) {
            int r = rg + 16 * j;
            float2 v01 = unpack2(acc1[p][j][0]);
            float2 v23 = unpack2(acc1[p][j][1]);
            float2* hp = (float2*)((char*)sm + IN_OFF) + r * HS2;
            float t0 = fmaxf(v01.x, 0.f), t1 = fmaxf(v01.y, 0.f);
            float t2 = fmaxf(v23.x, 0.f), t3 = fmaxf(v23.y, 0.f);
            hp[c0 + 0] = make_float2(t0, t0);
            hp[c0 + 1] = make_float2(t1, t1);
            hp[c0 + 2] = make_float2(t2, t2);
            hp[c0 + 3] = make_float2(t3, t3);
        }
    }
    __syncthreads();

    // GEMM2: out = hid @ W2 + b2, same structure (64 output cols)
    {
        int c0 = cg * 4;
        ull acc[4][2];
        ull i0 = pack2(b2s[c0], b2s[c0 + 1]);
        ull i1 = pack2(b2s[c0 + 2], b2s[c0 + 3]);
        #pragma unroll
        for (int j = 0; j < 4; j++) { acc[j][0] = i0; acc[j][1] = i1; }

        #pragma unroll 4
        for (int h2 = 0; h2 < H / 2; ++h2) {   // h = 2h2, 2h2+1
            ull ivA[4], ivB[4];
            #pragma unroll
            for (int j = 0; j < 4; j++)
                lds_v2u64(ivA[j], ivB[j],
                          sbase + IN_OFF + (unsigned)(rg + 16 * j) * (HS2 * 8) + h2 * 16);
            ull wA0, wA1, wB0, wB1;
            lds_v2u64(wA0, wA1, sbase + W2_OFF + (unsigned)(2 * h2)     * (64 * 4) + c0 * 4);
            lds_v2u64(wB0, wB1, sbase + W2_OFF + (unsigned)(2 * h2 + 1) * (64 * 4) + c0 * 4);
            #pragma unroll
            for (int j = 0; j < 4; j++) {
                fma2(acc[j][0], ivA[j], wA0);
                fma2(acc[j][1], ivA[j], wA1);
                fma2(acc[j][0], ivB[j], wB0);
                fma2(acc[j][1], ivB[j], wB1);
            }
        }
        #pragma unroll
        for (int j = 0; j < 4; j++) {
            int r = rg + 16 * j;
            if (r < nrows) {
                float2 v01 = unpack2(acc[j][0]);
                float2 v23 = unpack2(acc[j][1]);
                float4 v;
                if (RELU_OUT) {
                    v = make_float4(fmaxf(v01.x, 0.f), fmaxf(v01.y, 0.f),
                                    fmaxf(v23.x, 0.f), fmaxf(v23.y, 0.f));
                } else {
                    v = make_float4(v01.x, v01.y, v23.x, v23.y);
                }
                out4[(size_t)(row0 + r) * 16 + cg] = v;
            }
        }
    }
}

// ---------------------------------------------------------------------------
// Launch
// ---------------------------------------------------------------------------
static inline size_t mlp_smem(int H) {
    size_t bytes = (size_t)64 * 66 * 8      // in_dup (>= hid_dup)
                 + (size_t)64 * H * 4       // w1n
                 + (size_t)H * 64 * 4       // w2n
                 + (size_t)H * 4 + 256;     // b1s + b2s
    return bytes;
}

extern "C" void kernel_launch(void* const* d_in, const int* in_sizes, int n_in,
                              void* d_out, int out_size) {
    const float* x   = (const float*)d_in[0];
    const int*   ei  = (const int*)d_in[1];
    const float* ew  = (const float*)d_in[2];
    const float* w11 = (const float*)d_in[3];
    const float* b11 = (const float*)d_in[4];
    const float* w12 = (const float*)d_in[5];
    const float* b12 = (const float*)d_in[6];
    const float* w21 = (const float*)d_in[7];
    const float* b21 = (const float*)d_in[8];
    const float* w22 = (const float*)d_in[9];
    const float* b22 = (const float*)d_in[10];
    const float* w31 = (const float*)d_in[11];
    const float* b31 = (const float*)d_in[12];
    const float* w32 = (const float*)d_in[13];
    const float* b32 = (const float*)d_in[14];
    float* out = (float*)d_out;

    int N = in_sizes[0] / DIMF;
    int E = in_sizes[1] / 2;
    const int* src = ei;
    const int* dst = ei + E;

    float *agg, *h1, *h2;
    int *cnt, *rowptr, *cursor, *bsum;
    int2 *edata;
    cudaGetSymbolAddress((void**)&agg, g_agg);
    cudaGetSymbolAddress((void**)&h1, g_h1);
    cudaGetSymbolAddress((void**)&h2, g_h2);
    cudaGetSymbolAddress((void**)&cnt, g_cnt);
    cudaGetSymbolAddress((void**)&rowptr, g_rowptr);
    cudaGetSymbolAddress((void**)&cursor, g_cursor);
    cudaGetSymbolAddress((void**)&bsum, g_bsum);
    cudaGetSymbolAddress((void**)&edata, g_edata);

    size_t sm64  = mlp_smem(64);
    size_t sm128 = mlp_smem(128);
    cudaFuncSetAttribute(mlp_kernel<64, true>,  cudaFuncAttributeMaxDynamicSharedMemorySize, (int)sm64);
    cudaFuncSetAttribute(mlp_kernel<128, true>, cudaFuncAttributeMaxDynamicSharedMemorySize, (int)sm128);
    cudaFuncSetAttribute(mlp_kernel<64, false>, cudaFuncAttributeMaxDynamicSharedMemorySize, (int)sm64);

    int NB = (N + 255) / 256;                // scan blocks (<=512 required)
    int eb = (E + 255) / 256;
    int gb = (N * 16 + 255) / 256;
    int mb = (N + 63) / 64;

    // --- CSR build (by destination) ---
    zero_cnt_kernel<<<NB, 256>>>(cnt, N);
    hist_kernel<<<eb, 256>>>(dst, cnt, E);
    scan_partial_kernel<<<NB, 256>>>(cnt, bsum, N);
    scan_top_kernel<<<1, 512>>>(bsum, NB);
    scan_final_kernel<<<NB + 1, 256>>>(cnt, bsum, rowptr, cursor, N);
    fill_kernel<<<eb, 256>>>(src, dst, ew, cursor, edata, E);

    // --- Layer 1: 64 -> 64 -> 64, relu ---
    gather_kernel<<<gb, 256>>>((const float4*)x, rowptr, edata, (float4*)agg, N);
    mlp_kernel<64, true><<<mb, 256, sm64>>>((const float4*)agg,
        (const float4*)w11, b11, (const float4*)w12, b12, (float4*)h1, N);

    // --- Layer 2: 64 -> 128 -> 64, relu ---
    gather_kernel<<<gb, 256>>>((const float4*)h1, rowptr, edata, (float4*)agg, N);
    mlp_kernel<128, true><<<mb, 256, sm128>>>((const float4*)agg,
        (const float4*)w21, b21, (const float4*)w22, b22, (float4*)h2, N);

    // --- Layer 3: 64 -> 64 -> 64, no relu ---
    gather_kernel<<<gb, 256>>>((const float4*)h2, rowptr, edata, (float4*)agg, N);
    mlp_kernel<64, false><<<mb, 256, sm64>>>((const float4*)agg,
        (const float4*)w31, b31, (const float4*)w32, b32, (float4*)out, N);
}

// round 9
// speedup vs baseline: 1.1513x; 1.1513x over previous
#include <cuda_runtime.h>
#include <cuda_bf16.h>

// Problem constants (reference: N=100000, E=1000000, D=64)
#define MAXN 100000
#define MAXE 1000000
#define DIMF 64

// Scratch (device globals; no allocation allowed)
__device__ float g_h1[MAXN * DIMF];
__device__ float g_h2[MAXN * DIMF];
__device__ int   g_cnt[MAXN];
__device__ int   g_rowptr[MAXN + 1];
__device__ int   g_cursor[MAXN];
__device__ int2  g_edata[MAXE];          // {src, float_bits(w)} grouped by dst
__device__ int   g_bsum[512];

// ---------------------------------------------------------------------------
// CSR build: histogram -> exclusive scan -> fill
// ---------------------------------------------------------------------------
__global__ void zero_cnt_kernel(int* __restrict__ cnt, int N) {
    int i = blockIdx.x * blockDim.x + threadIdx.x;
    if (i < N) cnt[i] = 0;
}

__global__ void hist_kernel(const int* __restrict__ dst, int* __restrict__ cnt, int E) {
    int e = blockIdx.x * blockDim.x + threadIdx.x;
    if (e < E) atomicAdd(&cnt[dst[e]], 1);
}

__global__ void scan_partial_kernel(const int* __restrict__ cnt, int* __restrict__ bsum, int N) {
    __shared__ int sm[256];
    int i = blockIdx.x * 256 + threadIdx.x;
    sm[threadIdx.x] = (i < N) ? cnt[i] : 0;
    __syncthreads();
    for (int s = 128; s > 0; s >>= 1) {
        if (threadIdx.x < s) sm[threadIdx.x] += sm[threadIdx.x + s];
        __syncthreads();
    }
    if (threadIdx.x == 0) bsum[blockIdx.x] = sm[0];
}

// Single-warp exclusive scan of bsum (NB <= 512): 32-lane tiles + running carry
__global__ void scan_top_kernel(int* __restrict__ bsum, int NB) {
    int lane = threadIdx.x;          // 32 threads
    int carry = 0;
    for (int base = 0; base < NB; base += 32) {
        int i = base + lane;
        int v = (i < NB) ? bsum[i] : 0;
        int s = v;
        #pragma unroll
        for (int d = 1; d < 32; d <<= 1) {
            int t = __shfl_up_sync(0xFFFFFFFFu, s, d);
            if (lane >= d) s += t;
        }
        if (i < NB) bsum[i] = carry + s - v;   // exclusive
        int tile_sum = __shfl_sync(0xFFFFFFFFu, s, 31);
        carry += tile_sum;
    }
}

__global__ void scan_final_kernel(const int* __restrict__ cnt,
                                  const int* __restrict__ bsum,
                                  int* __restrict__ rowptr,
                                  int* __restrict__ cursor, int N) {
    __shared__ int sm[256];
    int t = threadIdx.x;
    int i = blockIdx.x * 256 + t;
    int v = (i < N) ? cnt[i] : 0;
    sm[t] = v;
    __syncthreads();
    for (int s = 1; s < 256; s <<= 1) {
        int add = (t >= s) ? sm[t - s] : 0;
        __syncthreads();
        sm[t] += add;
        __syncthreads();
    }
    int val = bsum[blockIdx.x] + sm[t] - v;   // exclusive prefix
    if (i < N) {
        rowptr[i] = val;
        cursor[i] = val;
    } else if (i == N) {
        rowptr[N] = val;                      // == E
    }
}

__global__ void fill_kernel(const int* __restrict__ src, const int* __restrict__ dst,
                            const float* __restrict__ ew,
                            int* __restrict__ cursor, int2* __restrict__ edata, int E) {
    int e = blockIdx.x * blockDim.x + threadIdx.x;
    if (e >= E) return;
    int d = dst[e];
    int p = atomicAdd(&cursor[d], 1);
    edata[p] = make_int2(src[e], __float_as_int(ew[e]));
}

// ---------------------------------------------------------------------------
// Fused layer kernel: gather (CSR, no atomics) + 2-layer MLP.
//
// Phase A: 16 groups x 16 lanes; group g gathers nodes r = g + 16*i
// (i=0..3): acc = x[n] + sum x[src]*w with shfl-distributed edges (16
// independent LDG.128 in flight). Result written straight into the
// transposed staging tile in_v[k4][r] -- no agg global round-trip.
// Phases B-D: byte-for-byte the R7 MLP (natural-layout weights, broadcast
// reads, 4x4 register tiles, hid reuses the in+w1 smem region).
// ---------------------------------------------------------------------------
template<int H, bool RELU_OUT>
__global__ void __launch_bounds__(256, 2) layer_kernel(
        const float4* __restrict__ x4,
        const int* __restrict__ rowptr,
        const int2* __restrict__ edata,
        const float4* __restrict__ w1, const float* __restrict__ b1,
        const float4* __restrict__ w2, const float* __restrict__ b2,
        float4* __restrict__ out4, int N) {
    constexpr int TR  = 64;
    constexpr int INS = 65;
    constexpr int NP  = H / 64;

    extern __shared__ float sm[];
    float4* in_v = (float4*)sm;               // 16 * INS float4 (in_v[k4][r])
    float*  w1n  = sm + 16 * INS * 4;         // 64 * H   natural: w1n[k*H+c]
    float4* hid4 = (float4*)sm;               // reuses in_v+w1n region
    float*  w2n  = w1n + 64 * H;              // H * 64   natural: w2n[h*64+c]
    float*  b1s  = w2n + H * 64;              // H
    float*  b2s  = b1s + H;                   // 64

    int tid  = threadIdx.x;
    int row0 = blockIdx.x * TR;
    int nrows = N - row0; if (nrows > TR) nrows = TR;

    // Weight/bias staging (conflict-free coalesced copies, natural layout)
    for (int i = tid; i < 64 * H / 4; i += 256) ((float4*)w1n)[i] = w1[i];
    for (int i = tid; i < H * 64 / 4; i += 256) ((float4*)w2n)[i] = w2[i];
    if (tid < H)  b1s[tid] = b1[tid];
    if (tid < 64) b2s[tid] = b2[tid];

    // Phase A: gather directly into in_v (transposed)
    {
        int g = tid >> 4;                     // group 0..15
        int c = tid & 15;                     // k4 chunk / edge slot
        unsigned gmask = 0xFFFFu << (threadIdx.x & 16);
        #pragma unroll
        for (int i = 0; i < 4; i++) {
            int r = g + 16 * i;
            float4 acc = make_float4(0.f, 0.f, 0.f, 0.f);
            if (r < nrows) {
                int n = row0 + r;
                int beg = __ldg(rowptr + n);
                int end = __ldg(rowptr + n + 1);
                acc = __ldg(&x4[(size_t)n * 16 + c]);   // GIN identity term
                for (int base = beg; base < end; base += 16) {
                    int e = base + c;
                    int2 ed = (e < end) ? __ldg(edata + e) : make_int2(0, 0);
                    #pragma unroll
                    for (int jj = 0; jj < 16; jj++) {
                        int s   = __shfl_sync(gmask, ed.x, jj, 16);
                        float w = __int_as_float(__shfl_sync(gmask, ed.y, jj, 16));
                        float4 v = __ldg(&x4[(size_t)s * 16 + c]);
                        acc.x += v.x * w; acc.y += v.y * w;
                        acc.z += v.z * w; acc.w += v.w * w;
                    }
                }
            }
            in_v[c * INS + r] = acc;          // k4 = c
        }
    }
    __syncthreads();

    const int rg = tid & 15;   // rows rg + 16j
    const int cg = tid >> 4;   // col group (uniform per half-warp -> broadcast)

    // GEMM1: acc1 = in @ W1 + b1, kept in registers
    float acc1[NP][4][4];
    #pragma unroll
    for (int p = 0; p < NP; p++) {
        int c0 = (p * 16 + cg) * 4;
        #pragma unroll
        for (int j = 0; j < 4; j++) {
            acc1[p][j][0] = b1s[c0];     acc1[p][j][1] = b1s[c0 + 1];
            acc1[p][j][2] = b1s[c0 + 2]; acc1[p][j][3] = b1s[c0 + 3];
        }
    }
    #pragma unroll
    for (int k4 = 0; k4 < 16; ++k4) {
        float4 iv[4];
        #pragma unroll
        for (int j = 0; j < 4; j++) iv[j] = in_v[k4 * INS + rg + 16 * j];
        #pragma unroll
        for (int p = 0; p < NP; p++) {
            int c0 = (p * 16 + cg) * 4;
            float4 wv0 = *(const float4*)(w1n + (k4 * 4 + 0) * H + c0);
            float4 wv1 = *(const float4*)(w1n + (k4 * 4 + 1) * H + c0);
            float4 wv2 = *(const float4*)(w1n + (k4 * 4 + 2) * H + c0);
            float4 wv3 = *(const float4*)(w1n + (k4 * 4 + 3) * H + c0);
            #pragma unroll
            for (int j = 0; j < 4; j++) {
                acc1[p][j][0] += iv[j].x * wv0.x + iv[j].y * wv1.x + iv[j].z * wv2.x + iv[j].w * wv3.x;
                acc1[p][j][1] += iv[j].x * wv0.y + iv[j].y * wv1.y + iv[j].z * wv2.y + iv[j].w * wv3.y;
                acc1[p][j][2] += iv[j].x * wv0.z + iv[j].y * wv1.z + iv[j].z * wv2.z + iv[j].w * wv3.z;
                acc1[p][j][3] += iv[j].x * wv0.w + iv[j].y * wv1.w + iv[j].z * wv2.w + iv[j].w * wv3.w;
            }
        }
    }
    __syncthreads();   // all reads of in_v / w1n complete

    // Store relu(hid) k-major: hid4[h4][r]  (reuses in_v+w1n region)
    #pragma unroll
    for (int p = 0; p < NP; p++) {
        #pragma unroll
        for (int j = 0; j < 4; j++) {
            hid4[(p * 16 + cg) * 64 + rg + 16 * j] = make_float4(
                fmaxf(acc1[p][j][0], 0.f), fmaxf(acc1[p][j][1], 0.f),
                fmaxf(acc1[p][j][2], 0.f), fmaxf(acc1[p][j][3], 0.f));
        }
    }
    __syncthreads();

    // GEMM2: out = hid @ W2 + b2
    {
        int c0 = cg * 4;
        float acc[4][4];
        #pragma unroll
        for (int j = 0; j < 4; j++) {
            acc[j][0] = b2s[c0];     acc[j][1] = b2s[c0 + 1];
            acc[j][2] = b2s[c0 + 2]; acc[j][3] = b2s[c0 + 3];
        }
        #pragma unroll
        for (int h4 = 0; h4 < H / 4; ++h4) {
            float4 hv[4];
            #pragma unroll
            for (int j = 0; j < 4; j++) hv[j] = hid4[h4 * 64 + rg + 16 * j];
            float4 wv0 = *(const float4*)(w2n + (h4 * 4 + 0) * 64 + c0);
            float4 wv1 = *(const float4*)(w2n + (h4 * 4 + 1) * 64 + c0);
            float4 wv2 = *(const float4*)(w2n + (h4 * 4 + 2) * 64 + c0);
            float4 wv3 = *(const float4*)(w2n + (h4 * 4 + 3) * 64 + c0);
            #pragma unroll
            for (int j = 0; j < 4; j++) {
                acc[j][0] += hv[j].x * wv0.x + hv[j].y * wv1.x + hv[j].z * wv2.x + hv[j].w * wv3.x;
                acc[j][1] += hv[j].x * wv0.y + hv[j].y * wv1.y + hv[j].z * wv2.y + hv[j].w * wv3.y;
                acc[j][2] += hv[j].x * wv0.z + hv[j].y * wv1.z + hv[j].z * wv2.z + hv[j].w * wv3.z;
                acc[j][3] += hv[j].x * wv0.w + hv[j].y * wv1.w + hv[j].z * wv2.w + hv[j].w * wv3.w;
            }
        }
        #pragma unroll
        for (int j = 0; j < 4; j++) {
            int r = rg + 16 * j;
            if (r < nrows) {
                float4 v;
                if (RELU_OUT) {
                    v = make_float4(fmaxf(acc[j][0], 0.f), fmaxf(acc[j][1], 0.f),
                                    fmaxf(acc[j][2], 0.f), fmaxf(acc[j][3], 0.f));
                } else {
                    v = make_float4(acc[j][0], acc[j][1], acc[j][2], acc[j][3]);
                }
                out4[(size_t)(row0 + r) * 16 + cg] = v;
            }
        }
    }
}

// ---------------------------------------------------------------------------
// Launch
// ---------------------------------------------------------------------------
static inline size_t mlp_smem(int H) {
    size_t region0 = 16 * 65 * 4 + (size_t)64 * H;  // in_v + w1n (>= hid)
    return (region0 + (size_t)H * 64 + H + 64) * sizeof(float);
}

extern "C" void kernel_launch(void* const* d_in, const int* in_sizes, int n_in,
                              void* d_out, int out_size) {
    const float* x   = (const float*)d_in[0];
    const int*   ei  = (const int*)d_in[1];
    const float* ew  = (const float*)d_in[2];
    const float* w11 = (const float*)d_in[3];
    const float* b11 = (const float*)d_in[4];
    const float* w12 = (const float*)d_in[5];
    const float* b12 = (const float*)d_in[6];
    const float* w21 = (const float*)d_in[7];
    const float* b21 = (const float*)d_in[8];
    const float* w22 = (const float*)d_in[9];
    const float* b22 = (const float*)d_in[10];
    const float* w31 = (const float*)d_in[11];
    const float* b31 = (const float*)d_in[12];
    const float* w32 = (const float*)d_in[13];
    const float* b32 = (const float*)d_in[14];
    float* out = (float*)d_out;

    int N = in_sizes[0] / DIMF;
    int E = in_sizes[1] / 2;
    const int* src = ei;
    const int* dst = ei + E;

    float *h1, *h2;
    int *cnt, *rowptr, *cursor, *bsum;
    int2 *edata;
    cudaGetSymbolAddress((void**)&h1, g_h1);
    cudaGetSymbolAddress((void**)&h2, g_h2);
    cudaGetSymbolAddress((void**)&cnt, g_cnt);
    cudaGetSymbolAddress((void**)&rowptr, g_rowptr);
    cudaGetSymbolAddress((void**)&cursor, g_cursor);
    cudaGetSymbolAddress((void**)&bsum, g_bsum);
    cudaGetSymbolAddress((void**)&edata, g_edata);

    size_t sm64  = mlp_smem(64);
    size_t sm128 = mlp_smem(128);
    cudaFuncSetAttribute(layer_kernel<64, true>,  cudaFuncAttributeMaxDynamicSharedMemorySize, (int)sm64);
    cudaFuncSetAttribute(layer_kernel<128, true>, cudaFuncAttributeMaxDynamicSharedMemorySize, (int)sm128);
    cudaFuncSetAttribute(layer_kernel<64, false>, cudaFuncAttributeMaxDynamicSharedMemorySize, (int)sm64);

    int NB = (N + 255) / 256;                // scan blocks (<=512 required)
    int eb = (E + 255) / 256;
    int mb = (N + 63) / 64;

    // --- CSR build (by destination) ---
    zero_cnt_kernel<<<NB, 256>>>(cnt, N);
    hist_kernel<<<eb, 256>>>(dst, cnt, E);
    scan_partial_kernel<<<NB, 256>>>(cnt, bsum, N);
    scan_top_kernel<<<1, 32>>>(bsum, NB);
    scan_final_kernel<<<NB + 1, 256>>>(cnt, bsum, rowptr, cursor, N);
    fill_kernel<<<eb, 256>>>(src, dst, ew, cursor, edata, E);

    // --- Layer 1: 64 -> 64 -> 64, relu ---
    layer_kernel<64, true><<<mb, 256, sm64>>>((const float4*)x, rowptr, edata,
        (const float4*)w11, b11, (const float4*)w12, b12, (float4*)h1, N);

    // --- Layer 2: 64 -> 128 -> 64, relu ---
    layer_kernel<128, true><<<mb, 256, sm128>>>((const float4*)h1, rowptr, edata,
        (const float4*)w21, b21, (const float4*)w22, b22, (float4*)h2, N);

    // --- Layer 3: 64 -> 64 -> 64, no relu ---
    layer_kernel<64, false><<<mb, 256, sm64>>>((const float4*)h2, rowptr, edata,
        (const float4*)w31, b31, (const float4*)w32, b32, (float4*)out, N);
}

// round 10
// speedup vs baseline: 1.2605x; 1.0948x over previous
#include <cuda_runtime.h>
#include <cuda_bf16.h>
#include <cstdint>

// Problem constants (reference: N=100000, E=1000000, D=64)
#define MAXN 100000
#define MAXE 1000000
#define DIMF 64

// Scratch (device globals; no allocation allowed)
__device__ float g_agg[MAXN * DIMF];
__device__ float g_h1[MAXN * DIMF];
__device__ float g_h2[MAXN * DIMF];
__device__ int   g_cnt[MAXN];
__device__ int   g_rowptr[MAXN + 1];
__device__ int   g_cursor[MAXN];
__device__ int2  g_edata[MAXE];          // {src, float_bits(w)} grouped by dst
__device__ int   g_bsum[512];

// ---------------------------------------------------------------------------
// TF32 helpers
// ---------------------------------------------------------------------------
__device__ __forceinline__ uint32_t f2tf(float a) {
    uint32_t r; asm("cvt.rna.tf32.f32 %0, %1;" : "=r"(r) : "f"(a)); return r;
}
__device__ __forceinline__ void tf_split(float a, uint32_t& hi, uint32_t& lo) {
    hi = f2tf(a);
    lo = f2tf(a - __uint_as_float(hi));
}
__device__ __forceinline__ void mma_tf32(float c[4],
                                         uint32_t a0, uint32_t a1, uint32_t a2, uint32_t a3,
                                         uint32_t b0, uint32_t b1) {
    asm volatile(
        "mma.sync.aligned.m16n8k8.row.col.f32.tf32.tf32.f32 "
        "{%0,%1,%2,%3}, {%4,%5,%6,%7}, {%8,%9}, {%0,%1,%2,%3};"
        : "+f"(c[0]), "+f"(c[1]), "+f"(c[2]), "+f"(c[3])
        : "r"(a0), "r"(a1), "r"(a2), "r"(a3), "r"(b0), "r"(b1));
}

// ---------------------------------------------------------------------------
// CSR build: histogram -> exclusive scan -> fill
// ---------------------------------------------------------------------------
__global__ void zero_cnt_kernel(int* __restrict__ cnt, int N) {
    int i = blockIdx.x * blockDim.x + threadIdx.x;
    if (i < N) cnt[i] = 0;
}

__global__ void hist_kernel(const int* __restrict__ dst, int* __restrict__ cnt, int E) {
    int e = blockIdx.x * blockDim.x + threadIdx.x;
    if (e < E) atomicAdd(&cnt[dst[e]], 1);
}

__global__ void scan_partial_kernel(const int* __restrict__ cnt, int* __restrict__ bsum, int N) {
    __shared__ int sm[256];
    int i = blockIdx.x * 256 + threadIdx.x;
    sm[threadIdx.x] = (i < N) ? cnt[i] : 0;
    __syncthreads();
    for (int s = 128; s > 0; s >>= 1) {
        if (threadIdx.x < s) sm[threadIdx.x] += sm[threadIdx.x + s];
        __syncthreads();
    }
    if (threadIdx.x == 0) bsum[blockIdx.x] = sm[0];
}

__global__ void scan_top_kernel(int* __restrict__ bsum, int NB) {
    int lane = threadIdx.x;          // 32 threads
    int carry = 0;
    for (int base = 0; base < NB; base += 32) {
        int i = base + lane;
        int v = (i < NB) ? bsum[i] : 0;
        int s = v;
        #pragma unroll
        for (int d = 1; d < 32; d <<= 1) {
            int t = __shfl_up_sync(0xFFFFFFFFu, s, d);
            if (lane >= d) s += t;
        }
        if (i < NB) bsum[i] = carry + s - v;   // exclusive
        carry += __shfl_sync(0xFFFFFFFFu, s, 31);
    }
}

__global__ void scan_final_kernel(const int* __restrict__ cnt,
                                  const int* __restrict__ bsum,
                                  int* __restrict__ rowptr,
                                  int* __restrict__ cursor, int N) {
    __shared__ int sm[256];
    int t = threadIdx.x;
    int i = blockIdx.x * 256 + t;
    int v = (i < N) ? cnt[i] : 0;
    sm[t] = v;
    __syncthreads();
    for (int s = 1; s < 256; s <<= 1) {
        int add = (t >= s) ? sm[t - s] : 0;
        __syncthreads();
        sm[t] += add;
        __syncthreads();
    }
    int val = bsum[blockIdx.x] + sm[t] - v;   // exclusive prefix
    if (i < N) {
        rowptr[i] = val;
        cursor[i] = val;
    } else if (i == N) {
        rowptr[N] = val;                      // == E
    }
}

__global__ void fill_kernel(const int* __restrict__ src, const int* __restrict__ dst,
                            const float* __restrict__ ew,
                            int* __restrict__ cursor, int2* __restrict__ edata, int E) {
    int e = blockIdx.x * blockDim.x + threadIdx.x;
    if (e >= E) return;
    int d = dst[e];
    int p = atomicAdd(&cursor[d], 1);
    edata[p] = make_int2(src[e], __float_as_int(ew[e]));
}

// ---------------------------------------------------------------------------
// Gather-aggregate: agg[n] = x[n] + sum_{e in csr(n)} x[src_e] * w_e
// (unchanged R6/R7 winner)
// ---------------------------------------------------------------------------
__global__ void gather_kernel(const float4* __restrict__ x4,
                              const int* __restrict__ rowptr,
                              const int2* __restrict__ edata,
                              float4* __restrict__ agg, int N) {
    int idx = blockIdx.x * blockDim.x + threadIdx.x;
    int n = idx >> 4;
    if (n >= N) return;
    int c = idx & 15;
    unsigned gmask = 0xFFFFu << (threadIdx.x & 16);   // this 16-lane group

    int beg = __ldg(rowptr + n);
    int end = __ldg(rowptr + n + 1);
    float4 acc = x4[(size_t)n * 16 + c];    // GIN identity term

    for (int base = beg; base < end; base += 16) {
        int e = base + c;
        int2 ed = (e < end) ? __ldg(edata + e) : make_int2(0, 0);
        #pragma unroll
        for (int i = 0; i < 16; i++) {
            int s   = __shfl_sync(gmask, ed.x, i, 16);
            float w = __int_as_float(__shfl_sync(gmask, ed.y, i, 16));
            float4 v = __ldg(&x4[(size_t)s * 16 + c]);
            acc.x += v.x * w; acc.y += v.y * w;
            acc.z += v.z * w; acc.w += v.w * w;
        }
    }
    agg[(size_t)n * 16 + c] = acc;
}

// ---------------------------------------------------------------------------
// Tensor-core MLP (split-TF32): out = [relu]( relu(agg @ W1 + b1) @ W2 + b2 )
//
// mma.sync.m16n8k8.tf32 with 2-term split (hi+lo): D += Ah*Bh + Ah*Bl + Al*Bh
// -> error ~2^-22 per product, fp32 accumulate (rel_err ~1e-6).
// 64 rows/block, 8 warps: warp w -> m-tile (w>>1), n-half (w&1).
// Smem strides: A-tiles (in_s, hid) stride H?+4 == 4 mod 32 -> fragment loads
// hit banks 4r+c (distinct); W tiles stride +8 == 8 mod 32 -> banks 8k+n
// (distinct). hid overlays in_s+w1 after GEMM1 (values held in regs).
// ---------------------------------------------------------------------------
template<int H, bool RELU_OUT>
__global__ void __launch_bounds__(256, 2) mlp_tc_kernel(
        const float4* __restrict__ agg4,
        const float* __restrict__ w1, const float* __restrict__ b1,
        const float* __restrict__ w2, const float* __restrict__ b2,
        float* __restrict__ out, int N) {
    constexpr int TR   = 64;
    constexpr int INS  = 68;        // in_s stride (floats), ==4 mod 32
    constexpr int W1S  = H + 8;     // w1 stride, ==8 mod 32
    constexpr int HS   = H + 4;     // hid stride, ==4 mod 32
    constexpr int W2S  = 72;        // w2 stride, ==8 mod 32
    constexpr int IN_SZ = TR * INS;            // floats
    constexpr int W1_SZ = 64 * W1S;
    constexpr int NT1  = H / 16;    // n-tiles per warp in GEMM1 (4 or 8)
    constexpr int KS2  = H / 8;     // k-steps in GEMM2

    extern __shared__ float sm[];
    float* in_s = sm;                          // [64][INS]
    float* w1n  = sm + IN_SZ;                  // [64][W1S]
    float* hid  = sm;                          // [64][HS], overlays in_s+w1n
    float* w2n  = sm + IN_SZ + W1_SZ;          // [H][W2S]
    float* b1s  = w2n + H * W2S;               // H
    float* b2s  = b1s + H;                     // 64
    static_assert(TR * HS <= IN_SZ + W1_SZ, "hid overlay must fit");

    int tid  = threadIdx.x;
    int row0 = blockIdx.x * TR;
    int nrows = N - row0; if (nrows > TR) nrows = TR;

    // Stage weights (natural [k][n] with padded stride) + biases
    for (int i = tid; i < 64 * H; i += 256) {
        int k = i / H, n = i % H;
        w1n[k * W1S + n] = w1[i];
    }
    for (int i = tid; i < H * 64; i += 256) {
        int h = i / 64, n = i % 64;
        w2n[h * W2S + n] = w2[i];
    }
    if (tid < H)  b1s[tid] = b1[tid];
    if (tid < 64) b2s[tid] = b2[tid];

    // Stage input rows (row-major, stride INS; zero-pad tail rows)
    for (int i = tid; i < TR * 16; i += 256) {
        int r = i >> 4, k4 = i & 15;
        float4 v = make_float4(0.f, 0.f, 0.f, 0.f);
        if (r < nrows) v = agg4[(size_t)(row0 + r) * 16 + k4];
        *(float4*)(in_s + r * INS + k4 * 4) = v;
    }
    __syncthreads();

    const int wid  = tid >> 5;
    const int lane = tid & 31;
    const int g    = lane >> 2;     // groupID (row within tile)
    const int tg   = lane & 3;      // thread-in-group (col)
    const int m0   = (wid >> 1) * 16;
    const int nb1  = (wid & 1) * NT1 * 8;   // GEMM1 n-tile base

    // ---- GEMM1: hid = relu(in @ W1 + b1) ----
    float c1[NT1][4];
    #pragma unroll
    for (int j = 0; j < NT1; j++) {
        int n0 = nb1 + j * 8;
        float bv0 = b1s[n0 + 2 * tg], bv1 = b1s[n0 + 2 * tg + 1];
        c1[j][0] = bv0; c1[j][1] = bv1; c1[j][2] = bv0; c1[j][3] = bv1;
    }
    #pragma unroll
    for (int kk = 0; kk < 8; kk++) {        // K = 64
        int k0 = kk * 8;
        uint32_t ah[4], al[4];
        tf_split(in_s[(m0 + g)     * INS + k0 + tg],     ah[0], al[0]);
        tf_split(in_s[(m0 + g + 8) * INS + k0 + tg],     ah[1], al[1]);
        tf_split(in_s[(m0 + g)     * INS + k0 + tg + 4], ah[2], al[2]);
        tf_split(in_s[(m0 + g + 8) * INS + k0 + tg + 4], ah[3], al[3]);
        #pragma unroll
        for (int j = 0; j < NT1; j++) {
            int n0 = nb1 + j * 8;
            uint32_t bh0, bl0, bh1, bl1;
            tf_split(w1n[(k0 + tg)     * W1S + n0 + g], bh0, bl0);
            tf_split(w1n[(k0 + tg + 4) * W1S + n0 + g], bh1, bl1);
            mma_tf32(c1[j], ah[0], ah[1], ah[2], ah[3], bh0, bh1);
            mma_tf32(c1[j], ah[0], ah[1], ah[2], ah[3], bl0, bl1);
            mma_tf32(c1[j], al[0], al[1], al[2], al[3], bh0, bh1);
        }
    }
    __syncthreads();   // all reads of in_s / w1n done

    // Write relu(hid), overlaying in_s+w1n
    #pragma unroll
    for (int j = 0; j < NT1; j++) {
        int n0 = nb1 + j * 8 + 2 * tg;
        *(float2*)(hid + (m0 + g)     * HS + n0) =
            make_float2(fmaxf(c1[j][0], 0.f), fmaxf(c1[j][1], 0.f));
        *(float2*)(hid + (m0 + g + 8) * HS + n0) =
            make_float2(fmaxf(c1[j][2], 0.f), fmaxf(c1[j][3], 0.f));
    }
    __syncthreads();

    // ---- GEMM2: out = hid @ W2 + b2 ----
    {
        constexpr int NT2 = 4;               // 8 n-tiles, 2 warps per m
        int nb2 = (wid & 1) * 32;
        float c2[NT2][4];
        #pragma unroll
        for (int j = 0; j < NT2; j++) {
            int n0 = nb2 + j * 8;
            float bv0 = b2s[n0 + 2 * tg], bv1 = b2s[n0 + 2 * tg + 1];
            c2[j][0] = bv0; c2[j][1] = bv1; c2[j][2] = bv0; c2[j][3] = bv1;
        }
        #pragma unroll
        for (int kk = 0; kk < KS2; kk++) {
            int k0 = kk * 8;
            uint32_t ah[4], al[4];
            tf_split(hid[(m0 + g)     * HS + k0 + tg],     ah[0], al[0]);
            tf_split(hid[(m0 + g + 8) * HS + k0 + tg],     ah[1], al[1]);
            tf_split(hid[(m0 + g)     * HS + k0 + tg + 4], ah[2], al[2]);
            tf_split(hid[(m0 + g + 8) * HS + k0 + tg + 4], ah[3], al[3]);
            #pragma unroll
            for (int j = 0; j < NT2; j++) {
                int n0 = nb2 + j * 8;
                uint32_t bh0, bl0, bh1, bl1;
                tf_split(w2n[(k0 + tg)     * W2S + n0 + g], bh0, bl0);
                tf_split(w2n[(k0 + tg + 4) * W2S + n0 + g], bh1, bl1);
                mma_tf32(c2[j], ah[0], ah[1], ah[2], ah[3], bh0, bh1);
                mma_tf32(c2[j], ah[0], ah[1], ah[2], ah[3], bl0, bl1);
                mma_tf32(c2[j], al[0], al[1], al[2], al[3], bh0, bh1);
            }
        }
        // Write output (float2 per row-fragment, guarded)
        int r0 = m0 + g, r1 = m0 + g + 8;
        #pragma unroll
        for (int j = 0; j < NT2; j++) {
            int n0 = nb2 + j * 8 + 2 * tg;
            if (r0 < nrows) {
                float2 v = make_float2(c2[j][0], c2[j][1]);
                if (RELU_OUT) { v.x = fmaxf(v.x, 0.f); v.y = fmaxf(v.y, 0.f); }
                *(float2*)(out + (size_t)(row0 + r0) * 64 + n0) = v;
            }
            if (r1 < nrows) {
                float2 v = make_float2(c2[j][2], c2[j][3]);
                if (RELU_OUT) { v.x = fmaxf(v.x, 0.f); v.y = fmaxf(v.y, 0.f); }
                *(float2*)(out + (size_t)(row0 + r1) * 64 + n0) = v;
            }
        }
    }
}

// ---------------------------------------------------------------------------
// Launch
// ---------------------------------------------------------------------------
static inline size_t mlp_smem(int H) {
    size_t floats = (size_t)64 * 68            // in_s
                  + (size_t)64 * (H + 8)       // w1n
                  + (size_t)H * 72             // w2n
                  + H + 64;                    // biases
    return floats * sizeof(float);
}

extern "C" void kernel_launch(void* const* d_in, const int* in_sizes, int n_in,
                              void* d_out, int out_size) {
    const float* x   = (const float*)d_in[0];
    const int*   ei  = (const int*)d_in[1];
    const float* ew  = (const float*)d_in[2];
    const float* w11 = (const float*)d_in[3];
    const float* b11 = (const float*)d_in[4];
    const float* w12 = (const float*)d_in[5];
    const float* b12 = (const float*)d_in[6];
    const float* w21 = (const float*)d_in[7];
    const float* b21 = (const float*)d_in[8];
    const float* w22 = (const float*)d_in[9];
    const float* b22 = (const float*)d_in[10];
    const float* w31 = (const float*)d_in[11];
    const float* b31 = (const float*)d_in[12];
    const float* w32 = (const float*)d_in[13];
    const float* b32 = (const float*)d_in[14];
    float* out = (float*)d_out;

    int N = in_sizes[0] / DIMF;
    int E = in_sizes[1] / 2;
    const int* src = ei;
    const int* dst = ei + E;

    float *agg, *h1, *h2;
    int *cnt, *rowptr, *cursor, *bsum;
    int2 *edata;
    cudaGetSymbolAddress((void**)&agg, g_agg);
    cudaGetSymbolAddress((void**)&h1, g_h1);
    cudaGetSymbolAddress((void**)&h2, g_h2);
    cudaGetSymbolAddress((void**)&cnt, g_cnt);
    cudaGetSymbolAddress((void**)&rowptr, g_rowptr);
    cudaGetSymbolAddress((void**)&cursor, g_cursor);
    cudaGetSymbolAddress((void**)&bsum, g_bsum);
    cudaGetSymbolAddress((void**)&edata, g_edata);

    size_t sm64  = mlp_smem(64);
    size_t sm128 = mlp_smem(128);
    cudaFuncSetAttribute(mlp_tc_kernel<64, true>,  cudaFuncAttributeMaxDynamicSharedMemorySize, (int)sm64);
    cudaFuncSetAttribute(mlp_tc_kernel<128, true>, cudaFuncAttributeMaxDynamicSharedMemorySize, (int)sm128);
    cudaFuncSetAttribute(mlp_tc_kernel<64, false>, cudaFuncAttributeMaxDynamicSharedMemorySize, (int)sm64);

    int NB = (N + 255) / 256;                // scan blocks (<=512 required)
    int eb = (E + 255) / 256;
    int gb = (N * 16 + 255) / 256;
    int mb = (N + 63) / 64;

    // --- CSR build (by destination) ---
    zero_cnt_kernel<<<NB, 256>>>(cnt, N);
    hist_kernel<<<eb, 256>>>(dst, cnt, E);
    scan_partial_kernel<<<NB, 256>>>(cnt, bsum, N);
    scan_top_kernel<<<1, 32>>>(bsum, NB);
    scan_final_kernel<<<NB + 1, 256>>>(cnt, bsum, rowptr, cursor, N);
    fill_kernel<<<eb, 256>>>(src, dst, ew, cursor, edata, E);

    // --- Layer 1: 64 -> 64 -> 64, relu ---
    gather_kernel<<<gb, 256>>>((const float4*)x, rowptr, edata, (float4*)agg, N);
    mlp_tc_kernel<64, true><<<mb, 256, sm64>>>((const float4*)agg, w11, b11, w12, b12, h1, N);

    // --- Layer 2: 64 -> 128 -> 64, relu ---
    gather_kernel<<<gb, 256>>>((const float4*)h1, rowptr, edata, (float4*)agg, N);
    mlp_tc_kernel<128, true><<<mb, 256, sm128>>>((const float4*)agg, w21, b21, w22, b22, h2, N);

    // --- Layer 3: 64 -> 64 -> 64, no relu ---
    gather_kernel<<<gb, 256>>>((const float4*)h2, rowptr, edata, (float4*)agg, N);
    mlp_tc_kernel<64, false><<<mb, 256, sm64>>>((const float4*)agg, w31, b31, w32, b32, out, N);
}